// round 14
// baseline (speedup 1.0000x reference)
#include <cuda_runtime.h>
#include <cstdint>
#include <cmath>

// ---------------------------------------------------------------------------
// Instant-NGP HashEncoder: B=2,097,152 points, D=3, L=16, C=2,
// base_res=16, desired=2048, log2_hashmap=19.
//
// R14: hashed-level gathers use __ldcg (L2-only, no L1 fill) — the 44MB
// hashed hot set has ~1% L1 hit rate, so L1 fills are pure overhead on the
// binding l1tex fill pipe AND they thrash the dense tables. Dense pair
// table / inputs / metadata keep __ldg (.nc, L1-cached) and now own L1.
// Everything else identical to R13 (XOR-chunk merging, dense pair table,
// host-computed scales, 8 threads/point, coalesced float4 stores).
// ---------------------------------------------------------------------------

#define NLEVELS 16
#define HASH_MASK 524287u
#define P2 2654435761u
#define P3 805459861u
#define DENSE_PARAMS 330952   // OFFSETS[5]: total entries of dense levels 0..4

// level tables (verified: total params == 6,098,120 matches reference)
__device__ const unsigned g_res[NLEVELS] = {16u, 23u, 31u, 43u, 59u, 81u, 112u, 154u,
                                            213u, 295u, 407u, 562u, 777u, 1073u, 1483u, 2048u};
__device__ const unsigned g_off[NLEVELS] = {0u, 4096u, 16264u, 46056u, 125568u,
                                            330952u, 855240u, 1379528u, 1903816u,
                                            2428104u, 2952392u, 3476680u, 4000968u,
                                            4525256u, 5049544u, 5573832u};

struct Scales { float s[NLEVELS]; };

// dense pair table: g_dpair[i] = (emb[i].x, emb[i].y, emb[i+1].x, emb[i+1].y)
__device__ float4 g_dpair[DENSE_PARAMS];

__global__ __launch_bounds__(256)
void build_dense_pairs_kernel(const float2* __restrict__ emb) {
    int i = blockIdx.x * blockDim.x + threadIdx.x;
    if (i >= DENSE_PARAMS) return;
    const float2 a = __ldg(&emb[i]);
    const float2 b = __ldg(&emb[i + 1]);   // i+1 <= DENSE_PARAMS < TOTAL, safe
    g_dpair[i] = make_float4(a.x, a.y, b.x, b.y);
}

__device__ __forceinline__ void encode_level(int l, float scale,
                                             float x, float y, float z,
                                             const float2* __restrict__ emb,
                                             float& ax, float& ay)
{
    const unsigned res = __ldg(&g_res[l]);
    const unsigned rm1 = res - 1u;
    const unsigned off = __ldg(&g_off[l]);

    const float px = __fadd_rn(__fmul_rn(x, scale), 0.5f);
    const float py = __fadd_rn(__fmul_rn(y, scale), 0.5f);
    const float pz = __fadd_rn(__fmul_rn(z, scale), 0.5f);

    const float fxg = floorf(px), fyg = floorf(py), fzg = floorf(pz);
    const float fx = px - fxg, fy = py - fyg, fz = pz - fzg;
    const unsigned gx = (unsigned)fxg, gy = (unsigned)fyg, gz = (unsigned)fzg;

    const float wx0 = 1.0f - fx, wx1 = fx;
    const float wy_[2] = {1.0f - fy, fy};
    const float wz_[2] = {1.0f - fz, fz};

    const unsigned cx0 = min(gx, rm1), cx1 = min(gx + 1u, rm1);
    const unsigned cy0 = min(gy, rm1), cy1 = min(gy + 1u, rm1);
    const unsigned cz0 = min(gz, rm1), cz1 = min(gz + 1u, rm1);

    ax = 0.0f; ay = 0.0f;

    if (l >= 5) {
        // ---- hashed level: XOR-chunk merging + L2-only loads (__ldcg).
        const unsigned hy0 = cy0 * P2, hy1 = cy1 * P2;
        const unsigned hz0 = cz0 * P3, hz1 = cz1 * P3;
        const float2* __restrict__ tab = emb + off;
        const float4* __restrict__ tab4 = reinterpret_cast<const float4*>(tab);
        unsigned byz[4] = {hy0 ^ hz0, hy1 ^ hz0, hy0 ^ hz1, hy1 ^ hz1};
#pragma unroll
        for (int p = 0; p < 4; ++p) {
            const unsigned by = p & 1u, bz = (p >> 1) & 1u;
            const float wyz = wy_[by] * wz_[bz];
            const float w0 = wx0 * wyz, w1 = wx1 * wyz;
            const unsigned i0 = (cx0 ^ byz[p]) & HASH_MASK;
            const unsigned i1 = (cx1 ^ byz[p]) & HASH_MASK;
            if ((i0 ^ i1) == 1u) {
                // one aligned 16B L2-only load covers both corners
                const float4 q = __ldcg(tab4 + (i0 >> 1));
                const bool sw = (i0 & 1u);          // i0 is the odd element?
                const float e0x = sw ? q.z : q.x;
                const float e0y = sw ? q.w : q.y;
                const float e1x = sw ? q.x : q.z;
                const float e1y = sw ? q.y : q.w;
                ax = fmaf(w0, e0x, ax);
                ay = fmaf(w0, e0y, ay);
                ax = fmaf(w1, e1x, ax);
                ay = fmaf(w1, e1y, ay);
            } else {
                const float2 e0 = __ldcg(tab + i0);
                const float2 e1 = __ldcg(tab + i1);
                ax = fmaf(w0, e0.x, ax);
                ay = fmaf(w0, e0.y, ay);
                ax = fmaf(w1, e1.x, ax);
                ay = fmaf(w1, e1.y, ay);
            }
        }
    } else {
        // ---- dense level: pair table (L1-cached, now unthrashed) ----
        const unsigned ry0 = cy0 * res, ry1 = cy1 * res;
        const unsigned rz0 = cz0 * res * res, rz1 = cz1 * res * res;
        const unsigned b0 = ry0 + rz0 + off, b1 = ry1 + rz0 + off;
        const unsigned b2 = ry0 + rz1 + off, b3 = ry1 + rz1 + off;
        unsigned bases[4] = {b0, b1, b2, b3};
        const bool noclamp = (cx1 == cx0 + 1u);
#pragma unroll
        for (int p = 0; p < 4; ++p) {
            const unsigned by = p & 1u, bz = (p >> 1) & 1u;
            const float wyz = wy_[by] * wz_[bz];
            const float w0 = wx0 * wyz, w1 = wx1 * wyz;
            const unsigned i0 = cx0 + bases[p];   // <= 330,946 < DENSE_PARAMS
            // one 16B load covers both x-corners: g_dpair[i0] = (emb[i0], emb[i0+1])
            const float4 q = __ldg(&g_dpair[i0]);
            if (noclamp) {
                ax = fmaf(w0, q.x, ax);
                ay = fmaf(w0, q.y, ay);
                ax = fmaf(w1, q.z, ax);
                ay = fmaf(w1, q.w, ay);
            } else {
                // x clamped: both corners are entry i0
                const float w = w0 + w1;
                ax = fmaf(w, q.x, ax);
                ay = fmaf(w, q.y, ay);
            }
        }
    }
}

__global__ __launch_bounds__(256)
void hash_encode_kernel8(const float* __restrict__ inputs,
                         const float2* __restrict__ emb,
                         float* __restrict__ out,
                         Scales sc,
                         int B)
{
    const int t = blockIdx.x * blockDim.x + threadIdx.x;
    const int point = t >> 3;
    const int slot  = t & 7;
    if (point >= B) return;

    // 8 lanes per point read the same xyz -> warp-broadcast
    const float x = __ldg(&inputs[point * 3 + 0]);
    const float y = __ldg(&inputs[point * 3 + 1]);
    const float z = __ldg(&inputs[point * 3 + 2]);

    const int l0 = 2 * slot;
    float a0x, a0y, a1x, a1y;
    encode_level(l0 + 0, sc.s[l0 + 0], x, y, z, emb, a0x, a0y);
    encode_level(l0 + 1, sc.s[l0 + 1], x, y, z, emb, a1x, a1y);

    // slot s writes floats [4s..4s+3] of the point's 32-float row:
    // warp covers 4 points -> 512B contiguous -> fully coalesced
    float4* __restrict__ dst =
        reinterpret_cast<float4*>(out + (size_t)point * (2 * NLEVELS)) + slot;
    *dst = make_float4(a0x, a0y, a1x, a1y);
}

extern "C" void kernel_launch(void* const* d_in, const int* in_sizes, int n_in,
                              void* d_out, int out_size) {
    const float*  inputs = (const float*)d_in[0];   // [B, 3]
    const float2* emb    = (const float2*)d_in[1];  // [TOTAL_PARAMS, 2]
    float*        out    = (float*)d_out;           // [B, 32]

    const int B = in_sizes[0] / 3;

    // scales on host: same float64 path as numpy (exp2(l*7/15)*16-1 -> f32)
    Scales sc;
    for (int l = 0; l < NLEVELS; ++l) {
        double s = exp2((double)l * (7.0 / 15.0)) * 16.0 - 1.0;
        sc.s[l] = (float)s;
    }

    const int bthreads = 256;
    const int bblocks = (DENSE_PARAMS + bthreads - 1) / bthreads;
    build_dense_pairs_kernel<<<bblocks, bthreads>>>(emb);

    const int threads = 256;
    const long long total = (long long)B * 8;
    const int blocks = (int)((total + threads - 1) / threads);
    hash_encode_kernel8<<<blocks, threads>>>(inputs, emb, out, sc, B);
}

// round 15
// speedup vs baseline: 1.0305x; 1.0305x over previous
#include <cuda_runtime.h>
#include <cstdint>
#include <cmath>

// ---------------------------------------------------------------------------
// Instant-NGP HashEncoder: B=2,097,152 points, D=3, L=16, C=2,
// base_res=16, desired=2048, log2_hashmap=19.
//
// R15: SPATIAL BUCKETING. Process points in Morton-bucket order (32^3
// buckets) so nearby threads/warps gather from nearby table entries ->
// hashed levels 5..11 become L1-resident for the bucket's region.
// Output still written to each point's original row (order-independent,
// deterministic). Permutation built per launch: zero -> histogram ->
// scan -> scatter (all graph-capturable, static __device__ scratch).
// Gathers back to __ldg (R14 showed L1 hits on hashed tables matter).
// Keeps: XOR-chunk hashed merging, dense pair table, host scales,
// 8 threads/point, per-point contiguous float4 stores.
// ---------------------------------------------------------------------------

#define NLEVELS 16
#define HASH_MASK 524287u
#define P2 2654435761u
#define P3 805459861u
#define DENSE_PARAMS 330952       // OFFSETS[5]: entries of dense levels 0..4
#define MAXB (1 << 21)            // 2,097,152 points
#define NBUCKETS 32768            // 32^3 Morton buckets

// level tables (verified: total params == 6,098,120 matches reference)
__device__ const unsigned g_res[NLEVELS] = {16u, 23u, 31u, 43u, 59u, 81u, 112u, 154u,
                                            213u, 295u, 407u, 562u, 777u, 1073u, 1483u, 2048u};
__device__ const unsigned g_off[NLEVELS] = {0u, 4096u, 16264u, 46056u, 125568u,
                                            330952u, 855240u, 1379528u, 1903816u,
                                            2428104u, 2952392u, 3476680u, 4000968u,
                                            4525256u, 5049544u, 5573832u};

struct Scales { float s[NLEVELS]; };

__device__ float4 g_dpair[DENSE_PARAMS];  // dense pair table
__device__ unsigned g_hist[NBUCKETS];
__device__ unsigned g_offsets[NBUCKETS];
__device__ int g_perm[MAXB];

// ---- Morton helpers -------------------------------------------------------
__device__ __forceinline__ unsigned part1by2(unsigned v) {
    v &= 0x3FFu;
    v = (v | (v << 16)) & 0x030000FFu;
    v = (v | (v << 8))  & 0x0300F00Fu;
    v = (v | (v << 4))  & 0x030C30C3u;
    v = (v | (v << 2))  & 0x09249249u;
    return v;
}

__device__ __forceinline__ unsigned bucket_of(float x, float y, float z) {
    unsigned bx = min((unsigned)(x * 32.0f), 31u);
    unsigned by = min((unsigned)(y * 32.0f), 31u);
    unsigned bz = min((unsigned)(z * 32.0f), 31u);
    return part1by2(bx) | (part1by2(by) << 1) | (part1by2(bz) << 2);
}

// ---- permutation pipeline -------------------------------------------------
__global__ __launch_bounds__(256)
void zero_hist_kernel() {
    int i = blockIdx.x * blockDim.x + threadIdx.x;
    if (i < NBUCKETS) g_hist[i] = 0u;
}

__global__ __launch_bounds__(256)
void hist_kernel(const float* __restrict__ inputs, int B) {
    int i = blockIdx.x * blockDim.x + threadIdx.x;
    if (i >= B) return;
    const float x = __ldg(&inputs[i * 3 + 0]);
    const float y = __ldg(&inputs[i * 3 + 1]);
    const float z = __ldg(&inputs[i * 3 + 2]);
    atomicAdd(&g_hist[bucket_of(x, y, z)], 1u);
}

// exclusive scan of g_hist -> g_offsets, single block of 1024 threads,
// each owning 32 consecutive buckets.
__global__ __launch_bounds__(1024)
void scan_kernel() {
    __shared__ unsigned sh[2][1024];
    const int tid = threadIdx.x;
    const int base = tid * 32;

    unsigned loc[32];
    unsigned run = 0;
#pragma unroll
    for (int i = 0; i < 32; ++i) {
        loc[i] = run;
        run += g_hist[base + i];
    }
    sh[0][tid] = run;
    __syncthreads();

    // double-buffered inclusive Hillis-Steele scan over 1024 partials
    int src = 0;
    for (int off = 1; off < 1024; off <<= 1) {
        const int dst = 1 - src;
        unsigned v = sh[src][tid];
        if (tid >= off) v += sh[src][tid - off];
        sh[dst][tid] = v;
        __syncthreads();
        src = dst;
    }
    const unsigned pre = (tid == 0) ? 0u : sh[src][tid - 1];  // exclusive

#pragma unroll
    for (int i = 0; i < 32; ++i)
        g_offsets[base + i] = pre + loc[i];
}

__global__ __launch_bounds__(256)
void scatter_kernel(const float* __restrict__ inputs, int B) {
    int i = blockIdx.x * blockDim.x + threadIdx.x;
    if (i >= B) return;
    const float x = __ldg(&inputs[i * 3 + 0]);
    const float y = __ldg(&inputs[i * 3 + 1]);
    const float z = __ldg(&inputs[i * 3 + 2]);
    const unsigned pos = atomicAdd(&g_offsets[bucket_of(x, y, z)], 1u);
    g_perm[pos] = i;
}

// ---- dense pair table -----------------------------------------------------
__global__ __launch_bounds__(256)
void build_dense_pairs_kernel(const float2* __restrict__ emb) {
    int i = blockIdx.x * blockDim.x + threadIdx.x;
    if (i >= DENSE_PARAMS) return;
    const float2 a = __ldg(&emb[i]);
    const float2 b = __ldg(&emb[i + 1]);
    g_dpair[i] = make_float4(a.x, a.y, b.x, b.y);
}

// ---- encode ---------------------------------------------------------------
__device__ __forceinline__ void encode_level(int l, float scale,
                                             float x, float y, float z,
                                             const float2* __restrict__ emb,
                                             float& ax, float& ay)
{
    const unsigned res = __ldg(&g_res[l]);
    const unsigned rm1 = res - 1u;
    const unsigned off = __ldg(&g_off[l]);

    const float px = __fadd_rn(__fmul_rn(x, scale), 0.5f);
    const float py = __fadd_rn(__fmul_rn(y, scale), 0.5f);
    const float pz = __fadd_rn(__fmul_rn(z, scale), 0.5f);

    const float fxg = floorf(px), fyg = floorf(py), fzg = floorf(pz);
    const float fx = px - fxg, fy = py - fyg, fz = pz - fzg;
    const unsigned gx = (unsigned)fxg, gy = (unsigned)fyg, gz = (unsigned)fzg;

    const float wx0 = 1.0f - fx, wx1 = fx;
    const float wy_[2] = {1.0f - fy, fy};
    const float wz_[2] = {1.0f - fz, fz};

    const unsigned cx0 = min(gx, rm1), cx1 = min(gx + 1u, rm1);
    const unsigned cy0 = min(gy, rm1), cy1 = min(gy + 1u, rm1);
    const unsigned cz0 = min(gz, rm1), cz1 = min(gz + 1u, rm1);

    ax = 0.0f; ay = 0.0f;

    if (l >= 5) {
        // hashed: XOR-chunk merging, L1-cached loads
        const unsigned hy0 = cy0 * P2, hy1 = cy1 * P2;
        const unsigned hz0 = cz0 * P3, hz1 = cz1 * P3;
        const float2* __restrict__ tab = emb + off;
        const float4* __restrict__ tab4 = reinterpret_cast<const float4*>(tab);
        unsigned byz[4] = {hy0 ^ hz0, hy1 ^ hz0, hy0 ^ hz1, hy1 ^ hz1};
#pragma unroll
        for (int p = 0; p < 4; ++p) {
            const unsigned by = p & 1u, bz = (p >> 1) & 1u;
            const float wyz = wy_[by] * wz_[bz];
            const float w0 = wx0 * wyz, w1 = wx1 * wyz;
            const unsigned i0 = (cx0 ^ byz[p]) & HASH_MASK;
            const unsigned i1 = (cx1 ^ byz[p]) & HASH_MASK;
            if ((i0 ^ i1) == 1u) {
                const float4 q = __ldg(tab4 + (i0 >> 1));
                const bool sw = (i0 & 1u);
                const float e0x = sw ? q.z : q.x;
                const float e0y = sw ? q.w : q.y;
                const float e1x = sw ? q.x : q.z;
                const float e1y = sw ? q.y : q.w;
                ax = fmaf(w0, e0x, ax);
                ay = fmaf(w0, e0y, ay);
                ax = fmaf(w1, e1x, ax);
                ay = fmaf(w1, e1y, ay);
            } else {
                const float2 e0 = __ldg(tab + i0);
                const float2 e1 = __ldg(tab + i1);
                ax = fmaf(w0, e0.x, ax);
                ay = fmaf(w0, e0.y, ay);
                ax = fmaf(w1, e1.x, ax);
                ay = fmaf(w1, e1.y, ay);
            }
        }
    } else {
        // dense: pair table, 100% merge
        const unsigned ry0 = cy0 * res, ry1 = cy1 * res;
        const unsigned rz0 = cz0 * res * res, rz1 = cz1 * res * res;
        unsigned bases[4] = {ry0 + rz0 + off, ry1 + rz0 + off,
                             ry0 + rz1 + off, ry1 + rz1 + off};
        const bool noclamp = (cx1 == cx0 + 1u);
#pragma unroll
        for (int p = 0; p < 4; ++p) {
            const unsigned by = p & 1u, bz = (p >> 1) & 1u;
            const float wyz = wy_[by] * wz_[bz];
            const float w0 = wx0 * wyz, w1 = wx1 * wyz;
            const float4 q = __ldg(&g_dpair[cx0 + bases[p]]);
            if (noclamp) {
                ax = fmaf(w0, q.x, ax);
                ay = fmaf(w0, q.y, ay);
                ax = fmaf(w1, q.z, ax);
                ay = fmaf(w1, q.w, ay);
            } else {
                const float w = w0 + w1;
                ax = fmaf(w, q.x, ax);
                ay = fmaf(w, q.y, ay);
            }
        }
    }
}

__global__ __launch_bounds__(256)
void hash_encode_kernel8(const float* __restrict__ inputs,
                         const float2* __restrict__ emb,
                         float* __restrict__ out,
                         Scales sc,
                         int B)
{
    const int t = blockIdx.x * blockDim.x + threadIdx.x;
    const int j = t >> 3;              // position in Morton order
    const int slot = t & 7;
    if (j >= B) return;

    const int point = g_perm[j];       // original point index

    const float x = __ldg(&inputs[point * 3 + 0]);
    const float y = __ldg(&inputs[point * 3 + 1]);
    const float z = __ldg(&inputs[point * 3 + 2]);

    const int l0 = 2 * slot;
    float a0x, a0y, a1x, a1y;
    encode_level(l0 + 0, sc.s[l0 + 0], x, y, z, emb, a0x, a0y);
    encode_level(l0 + 1, sc.s[l0 + 1], x, y, z, emb, a1x, a1y);

    // write to the point's ORIGINAL output row (128B contiguous per point)
    float4* __restrict__ dst =
        reinterpret_cast<float4*>(out + (size_t)point * (2 * NLEVELS)) + slot;
    *dst = make_float4(a0x, a0y, a1x, a1y);
}

extern "C" void kernel_launch(void* const* d_in, const int* in_sizes, int n_in,
                              void* d_out, int out_size) {
    const float*  inputs = (const float*)d_in[0];   // [B, 3]
    const float2* emb    = (const float2*)d_in[1];  // [TOTAL_PARAMS, 2]
    float*        out    = (float*)d_out;           // [B, 32]

    const int B = in_sizes[0] / 3;

    Scales sc;
    for (int l = 0; l < NLEVELS; ++l) {
        double s = exp2((double)l * (7.0 / 15.0)) * 16.0 - 1.0;
        sc.s[l] = (float)s;
    }

    const int T = 256;

    zero_hist_kernel<<<(NBUCKETS + T - 1) / T, T>>>();
    hist_kernel<<<(B + T - 1) / T, T>>>(inputs, B);
    scan_kernel<<<1, 1024>>>();
    scatter_kernel<<<(B + T - 1) / T, T>>>(inputs, B);

    build_dense_pairs_kernel<<<(DENSE_PARAMS + T - 1) / T, T>>>(emb);

    const long long total = (long long)B * 8;
    hash_encode_kernel8<<<(int)((total + T - 1) / T), T>>>(inputs, emb, out, sc, B);
}